// round 6
// baseline (speedup 1.0000x reference)
#include <cuda_runtime.h>
#include <cuda_bf16.h>

#define VOCAB 100000
#define EMB   300
#define BSZ   2048
#define SEQL  200
#define HID   128
#define OUTD  20

#define EMB4    (EMB / 4)        // 75 float4 per row
#define SPB     4                // samples per block
#define THREADS 320              // 10 warps; 300 gather threads + GEMM1 uses all 320
#define DCH     10               // d-chunks in GEMM1 (10 x 30 = 300)

// ---------------------------------------------------------------------------
// Fused kernel: embedding-bag mean -> relu(rep@W1+b1) -> @W2+b2
// Block: 4 samples.  Gather phase: 75 threads/sample, 8 gathers in flight
// each (LTS-cap limited).  MLP phases run on the block's smem rep and
// overlap with OTHER blocks' gathers (3 CTAs/SM).
// ---------------------------------------------------------------------------
__global__ __launch_bounds__(THREADS) void fused_kernel(
    const int*    __restrict__ x,        // [B, L]
    const int*    __restrict__ lengths,  // [B]
    const float4* __restrict__ emb4,     // [VOCAB, 75]
    const float*  __restrict__ W1,       // [EMB, HID]
    const float*  __restrict__ b1,       // [HID]
    const float*  __restrict__ W2,       // [HID, OUTD]
    const float*  __restrict__ b2,       // [OUTD]
    float*        __restrict__ out)      // [B, OUTD]
{
    __shared__ float repT[EMB][SPB];           // 4.8 KB  rep transposed
    __shared__ float hpart[DCH][SPB][HID];     // 20 KB   GEMM1 partials
    __shared__ float hbuf[SPB][HID];           // 2 KB    post-relu hidden

    const int tid = threadIdx.x;
    const int b0  = blockIdx.x * SPB;

    // ---------------- Phase 1: gather (300 of 320 threads) -----------------
    if (tid < SPB * EMB4) {
        const int s = tid / EMB4;
        const int d = tid - s * EMB4;
        const int b = b0 + s;

        const int4* xb4 = (const int4*)(x + (size_t)b * SEQL);

        float4 a0 = make_float4(0.f, 0.f, 0.f, 0.f);
        float4 a1 = a0, a2 = a0, a3 = a0, a4 = a0, a5 = a0, a6 = a0, a7 = a0;

        #pragma unroll 1
        for (int it = 0; it < 25; ++it) {
            const int4 ia = __ldg(xb4 + it * 2 + 0);
            const int4 ib = __ldg(xb4 + it * 2 + 1);
            const float4 v0 = __ldg(emb4 + (size_t)ia.x * EMB4 + d);
            const float4 v1 = __ldg(emb4 + (size_t)ia.y * EMB4 + d);
            const float4 v2 = __ldg(emb4 + (size_t)ia.z * EMB4 + d);
            const float4 v3 = __ldg(emb4 + (size_t)ia.w * EMB4 + d);
            const float4 v4 = __ldg(emb4 + (size_t)ib.x * EMB4 + d);
            const float4 v5 = __ldg(emb4 + (size_t)ib.y * EMB4 + d);
            const float4 v6 = __ldg(emb4 + (size_t)ib.z * EMB4 + d);
            const float4 v7 = __ldg(emb4 + (size_t)ib.w * EMB4 + d);
            a0.x += v0.x; a0.y += v0.y; a0.z += v0.z; a0.w += v0.w;
            a1.x += v1.x; a1.y += v1.y; a1.z += v1.z; a1.w += v1.w;
            a2.x += v2.x; a2.y += v2.y; a2.z += v2.z; a2.w += v2.w;
            a3.x += v3.x; a3.y += v3.y; a3.z += v3.z; a3.w += v3.w;
            a4.x += v4.x; a4.y += v4.y; a4.z += v4.z; a4.w += v4.w;
            a5.x += v5.x; a5.y += v5.y; a5.z += v5.z; a5.w += v5.w;
            a6.x += v6.x; a6.y += v6.y; a6.z += v6.z; a6.w += v6.w;
            a7.x += v7.x; a7.y += v7.y; a7.z += v7.z; a7.w += v7.w;
        }

        const float inv = 1.0f / (float)__ldg(lengths + b);
        const int dd = 4 * d;
        repT[dd + 0][s] = (a0.x + a1.x + a2.x + a3.x + a4.x + a5.x + a6.x + a7.x) * inv;
        repT[dd + 1][s] = (a0.y + a1.y + a2.y + a3.y + a4.y + a5.y + a6.y + a7.y) * inv;
        repT[dd + 2][s] = (a0.z + a1.z + a2.z + a3.z + a4.z + a5.z + a6.z + a7.z) * inv;
        repT[dd + 3][s] = (a0.w + a1.w + a2.w + a3.w + a4.w + a5.w + a6.w + a7.w) * inv;
    }
    __syncthreads();

    // ---------------- Phase 2: GEMM1 (all 320 threads) ---------------------
    // thread (jg, c): output cols 4jg..4jg+3, d-chunk c of 10 (30 rows each)
    {
        const int jg = tid & 31;
        const int c  = tid >> 5;               // 0..9
        const int d0 = c * 30;

        float4 acc[SPB];
        #pragma unroll
        for (int s = 0; s < SPB; ++s) acc[s] = make_float4(0.f, 0.f, 0.f, 0.f);

        const float4* W14 = (const float4*)W1;   // [EMB][32] float4

        float4 w = __ldg(&W14[(size_t)d0 * 32 + jg]);

        #pragma unroll 3
        for (int k = 0; k < 30; ++k) {
            const int d = d0 + k;
            const float4 wc = w;
            if (k + 1 < 30) w = __ldg(&W14[(size_t)(d + 1) * 32 + jg]);
            const float4 r = *(const float4*)&repT[d][0];   // broadcast LDS.128
            acc[0].x += r.x * wc.x; acc[0].y += r.x * wc.y; acc[0].z += r.x * wc.z; acc[0].w += r.x * wc.w;
            acc[1].x += r.y * wc.x; acc[1].y += r.y * wc.y; acc[1].z += r.y * wc.z; acc[1].w += r.y * wc.w;
            acc[2].x += r.z * wc.x; acc[2].y += r.z * wc.y; acc[2].z += r.z * wc.z; acc[2].w += r.z * wc.w;
            acc[3].x += r.w * wc.x; acc[3].y += r.w * wc.y; acc[3].z += r.w * wc.z; acc[3].w += r.w * wc.w;
        }

        #pragma unroll
        for (int s = 0; s < SPB; ++s)
            *(float4*)&hpart[c][s][4 * jg] = acc[s];
    }
    __syncthreads();

    // ---------------- Phase 3: combine + bias + relu ------------------------
    for (int i = tid; i < SPB * HID; i += THREADS) {
        const int s = i >> 7;
        const int j = i & (HID - 1);
        float v = __ldg(&b1[j]);
        #pragma unroll
        for (int c = 0; c < DCH; ++c) v += hpart[c][s][j];
        hbuf[s][j] = v > 0.0f ? v : 0.0f;
    }
    __syncthreads();

    // ---------------- Phase 4: GEMM2 ---------------------------------------
    if (tid < SPB * OUTD) {
        const int s = tid / OUTD;
        const int o = tid - s * OUTD;
        float a0 = __ldg(&b2[o]), a1 = 0.f, a2 = 0.f, a3 = 0.f;
        #pragma unroll
        for (int k = 0; k < HID; k += 4) {
            a0 += hbuf[s][k + 0] * __ldg(&W2[(size_t)(k + 0) * OUTD + o]);
            a1 += hbuf[s][k + 1] * __ldg(&W2[(size_t)(k + 1) * OUTD + o]);
            a2 += hbuf[s][k + 2] * __ldg(&W2[(size_t)(k + 2) * OUTD + o]);
            a3 += hbuf[s][k + 3] * __ldg(&W2[(size_t)(k + 3) * OUTD + o]);
        }
        out[(size_t)(b0 + s) * OUTD + o] = (a0 + a1) + (a2 + a3);
    }
}

extern "C" void kernel_launch(void* const* d_in, const int* in_sizes, int n_in,
                              void* d_out, int out_size)
{
    const int*    x       = (const int*)    d_in[0];
    const int*    lengths = (const int*)    d_in[1];
    const float4* emb4    = (const float4*) d_in[2];
    const float*  W1      = (const float*)  d_in[3];
    const float*  b1      = (const float*)  d_in[4];
    const float*  W2      = (const float*)  d_in[5];
    const float*  b2      = (const float*)  d_in[6];
    float*        out     = (float*)        d_out;

    fused_kernel<<<BSZ / SPB, THREADS>>>(x, lengths, emb4, W1, b1, W2, b2, out);
}

// round 7
// speedup vs baseline: 1.2526x; 1.2526x over previous
#include <cuda_runtime.h>
#include <cuda_bf16.h>

#define VOCAB 100000
#define EMB   300
#define BSZ   2048
#define SEQL  200
#define HID   128
#define OUTD  20

#define EMB4  (EMB / 4)          // 75 float4 per row
#define SPB2  8                  // samples per group in GEMM1
#define JCH   16                 // col-groups per half (16 x 4 = 64 cols)
#define DCH   16                 // d-chunks (15 x 19 + 1 x 15 = 300)

// scratch (device globals — no allocation allowed)
__device__ float4 g_rep4[BSZ * EMB4];        // [B, EMB] mean-pooled reps
__device__ float  g_h[BSZ][HID];             // post-relu hidden

// ---------------------------------------------------------------------------
// Kernel 1: embedding-bag mean.  At the LTS throughput cap — do not touch.
// ---------------------------------------------------------------------------
__global__ __launch_bounds__(256) void gather_kernel(
    const int*    __restrict__ x,        // [B, L]
    const int*    __restrict__ lengths,  // [B]
    const float4* __restrict__ emb4)     // [VOCAB, 75]
{
    const int gid = blockIdx.x * 256 + threadIdx.x;
    if (gid >= BSZ * EMB4) return;
    const int b = gid / EMB4;
    const int d = gid - b * EMB4;

    const int4* xb4 = (const int4*)(x + (size_t)b * SEQL);

    float4 a0 = make_float4(0.f, 0.f, 0.f, 0.f);
    float4 a1 = a0, a2 = a0, a3 = a0, a4 = a0, a5 = a0, a6 = a0, a7 = a0;

    #pragma unroll 1
    for (int it = 0; it < 25; ++it) {
        const int4 ia = __ldg(xb4 + it * 2 + 0);
        const int4 ib = __ldg(xb4 + it * 2 + 1);
        const float4 v0 = __ldg(emb4 + (size_t)ia.x * EMB4 + d);
        const float4 v1 = __ldg(emb4 + (size_t)ia.y * EMB4 + d);
        const float4 v2 = __ldg(emb4 + (size_t)ia.z * EMB4 + d);
        const float4 v3 = __ldg(emb4 + (size_t)ia.w * EMB4 + d);
        const float4 v4 = __ldg(emb4 + (size_t)ib.x * EMB4 + d);
        const float4 v5 = __ldg(emb4 + (size_t)ib.y * EMB4 + d);
        const float4 v6 = __ldg(emb4 + (size_t)ib.z * EMB4 + d);
        const float4 v7 = __ldg(emb4 + (size_t)ib.w * EMB4 + d);
        a0.x += v0.x; a0.y += v0.y; a0.z += v0.z; a0.w += v0.w;
        a1.x += v1.x; a1.y += v1.y; a1.z += v1.z; a1.w += v1.w;
        a2.x += v2.x; a2.y += v2.y; a2.z += v2.z; a2.w += v2.w;
        a3.x += v3.x; a3.y += v3.y; a3.z += v3.z; a3.w += v3.w;
        a4.x += v4.x; a4.y += v4.y; a4.z += v4.z; a4.w += v4.w;
        a5.x += v5.x; a5.y += v5.y; a5.z += v5.z; a5.w += v5.w;
        a6.x += v6.x; a6.y += v6.y; a6.z += v6.z; a6.w += v6.w;
        a7.x += v7.x; a7.y += v7.y; a7.z += v7.z; a7.w += v7.w;
    }

    const float inv = 1.0f / (float)__ldg(lengths + b);
    float4 r;
    r.x = (a0.x + a1.x + a2.x + a3.x + a4.x + a5.x + a6.x + a7.x) * inv;
    r.y = (a0.y + a1.y + a2.y + a3.y + a4.y + a5.y + a6.y + a7.y) * inv;
    r.z = (a0.z + a1.z + a2.z + a3.z + a4.z + a5.z + a6.z + a7.z) * inv;
    r.w = (a0.w + a1.w + a2.w + a3.w + a4.w + a5.w + a6.w + a7.w) * inv;
    g_rep4[gid] = r;
}

// ---------------------------------------------------------------------------
// Kernel 2: h = relu(rep @ W1 + b1), split over column halves.
// grid 512 = 256 sample-groups x 2 halves.  Thread (c, jg) owns 4 cols x 8
// samples, d-chunk c.  W1 via LDG.128 (32 FMA per load).
// ---------------------------------------------------------------------------
__global__ __launch_bounds__(256) void gemm1_kernel(
    const float* __restrict__ W1,   // [EMB, HID]
    const float* __restrict__ b1)   // [HID]
{
    __shared__ float repT[EMB][SPB2];            // 9.6 KB
    __shared__ float hpart[DCH][SPB2][64];       // 32 KB

    const int tid  = threadIdx.x;
    const int sg   = blockIdx.x >> 1;            // sample group 0..255
    const int half = blockIdx.x & 1;             // column half 0/1
    const int b0   = sg * SPB2;
    const float* rep = (const float*)g_rep4;

    // load rep tile (coalesced, transpose into smem)
    for (int i = tid; i < SPB2 * EMB; i += 256) {
        const int s = i / EMB;
        const int d = i - s * EMB;
        repT[d][s] = rep[(size_t)(b0 + s) * EMB + d];
    }
    __syncthreads();

    // GEMM1 half
    {
        const int jg = tid & (JCH - 1);          // 0..15 -> cols 4jg..4jg+3 of half
        const int c  = tid >> 4;                 // d-chunk 0..15
        const int d0 = c * 19;
        const int d1 = (c == 15) ? EMB : d0 + 19;

        const int jcol = half * (HID / 8) + jg;  // float4 column index 0..31

        float4 acc[SPB2];
        #pragma unroll
        for (int s = 0; s < SPB2; ++s) acc[s] = make_float4(0.f, 0.f, 0.f, 0.f);

        const float4* W14 = (const float4*)W1;   // [EMB][32] float4

        float4 w = __ldg(&W14[(size_t)d0 * 32 + jcol]);

        #pragma unroll 1
        for (int d = d0; d < d1; ++d) {
            const float4 wc = w;
            if (d + 1 < d1) w = __ldg(&W14[(size_t)(d + 1) * 32 + jcol]);
            const float4 r0 = *(const float4*)&repT[d][0];
            const float4 r1 = *(const float4*)&repT[d][4];
            acc[0].x += r0.x * wc.x; acc[0].y += r0.x * wc.y; acc[0].z += r0.x * wc.z; acc[0].w += r0.x * wc.w;
            acc[1].x += r0.y * wc.x; acc[1].y += r0.y * wc.y; acc[1].z += r0.y * wc.z; acc[1].w += r0.y * wc.w;
            acc[2].x += r0.z * wc.x; acc[2].y += r0.z * wc.y; acc[2].z += r0.z * wc.z; acc[2].w += r0.z * wc.w;
            acc[3].x += r0.w * wc.x; acc[3].y += r0.w * wc.y; acc[3].z += r0.w * wc.z; acc[3].w += r0.w * wc.w;
            acc[4].x += r1.x * wc.x; acc[4].y += r1.x * wc.y; acc[4].z += r1.x * wc.z; acc[4].w += r1.x * wc.w;
            acc[5].x += r1.y * wc.x; acc[5].y += r1.y * wc.y; acc[5].z += r1.y * wc.z; acc[5].w += r1.y * wc.w;
            acc[6].x += r1.z * wc.x; acc[6].y += r1.z * wc.y; acc[6].z += r1.z * wc.z; acc[6].w += r1.z * wc.w;
            acc[7].x += r1.w * wc.x; acc[7].y += r1.w * wc.y; acc[7].z += r1.w * wc.z; acc[7].w += r1.w * wc.w;
        }

        #pragma unroll
        for (int s = 0; s < SPB2; ++s)
            *(float4*)&hpart[c][s][4 * jg] = acc[s];
    }
    __syncthreads();

    // combine + bias + relu -> g_h
    for (int i = tid; i < SPB2 * 64; i += 256) {
        const int s = i >> 6;
        const int j = i & 63;
        float v = __ldg(&b1[half * 64 + j]);
        #pragma unroll
        for (int c = 0; c < DCH; ++c) v += hpart[c][s][j];
        g_h[b0 + s][half * 64 + j] = v > 0.0f ? v : 0.0f;
    }
}

// ---------------------------------------------------------------------------
// Kernel 3: logits = h @ W2 + b2.  One thread per (sample, output).
// ---------------------------------------------------------------------------
__global__ __launch_bounds__(256) void gemm2_kernel(
    const float* __restrict__ W2,   // [HID, OUTD]
    const float* __restrict__ b2,   // [OUTD]
    float*       __restrict__ out)  // [B, OUTD]
{
    const int gid = blockIdx.x * 256 + threadIdx.x;
    if (gid >= BSZ * OUTD) return;
    const int s = gid / OUTD;
    const int o = gid - s * OUTD;

    const float* hrow = g_h[s];
    float a0 = __ldg(&b2[o]), a1 = 0.f, a2 = 0.f, a3 = 0.f;
    #pragma unroll 4
    for (int k = 0; k < HID; k += 4) {
        a0 += hrow[k + 0] * __ldg(&W2[(size_t)(k + 0) * OUTD + o]);
        a1 += hrow[k + 1] * __ldg(&W2[(size_t)(k + 1) * OUTD + o]);
        a2 += hrow[k + 2] * __ldg(&W2[(size_t)(k + 2) * OUTD + o]);
        a3 += hrow[k + 3] * __ldg(&W2[(size_t)(k + 3) * OUTD + o]);
    }
    out[(size_t)s * OUTD + o] = (a0 + a1) + (a2 + a3);
}

extern "C" void kernel_launch(void* const* d_in, const int* in_sizes, int n_in,
                              void* d_out, int out_size)
{
    const int*    x       = (const int*)    d_in[0];
    const int*    lengths = (const int*)    d_in[1];
    const float4* emb4    = (const float4*) d_in[2];
    const float*  W1      = (const float*)  d_in[3];
    const float*  b1      = (const float*)  d_in[4];
    const float*  W2      = (const float*)  d_in[5];
    const float*  b2      = (const float*)  d_in[6];
    float*        out     = (float*)        d_out;

    const int gather_items = BSZ * EMB4;                    // 153600
    gather_kernel<<<(gather_items + 255) / 256, 256>>>(x, lengths, emb4);
    gemm1_kernel<<<(BSZ / SPB2) * 2, 256>>>(W1, b1);        // 512 blocks
    gemm2_kernel<<<(BSZ * OUTD + 255) / 256, 256>>>(W2, b2, out);  // 160 blocks
}

// round 8
// speedup vs baseline: 1.4303x; 1.1419x over previous
#include <cuda_runtime.h>
#include <cuda_bf16.h>

#define VOCAB 100000
#define EMB   300
#define BSZ   2048
#define SEQL  200
#define HID   128
#define OUTD  20

#define EMB4  (EMB / 4)          // 75 float4 per row
#define SPB2  4                  // samples per block in MLP -> grid 512
#define DCH   8                  // d-chunks (8 x 38 covers 300, last=34)

// rep scratch (device global — no allocation allowed)
__device__ float4 g_rep4[BSZ * EMB4];

// ---------------------------------------------------------------------------
// Kernel 1: embedding-bag mean.  At the LTS/DRAM mixed roofline — unchanged.
// ---------------------------------------------------------------------------
__global__ __launch_bounds__(256) void gather_kernel(
    const int*    __restrict__ x,        // [B, L]
    const int*    __restrict__ lengths,  // [B]
    const float4* __restrict__ emb4)     // [VOCAB, 75]
{
    const int gid = blockIdx.x * 256 + threadIdx.x;
    if (gid >= BSZ * EMB4) return;
    const int b = gid / EMB4;
    const int d = gid - b * EMB4;

    const int4* xb4 = (const int4*)(x + (size_t)b * SEQL);

    float4 a0 = make_float4(0.f, 0.f, 0.f, 0.f);
    float4 a1 = a0, a2 = a0, a3 = a0, a4 = a0, a5 = a0, a6 = a0, a7 = a0;

    #pragma unroll 1
    for (int it = 0; it < 25; ++it) {
        const int4 ia = __ldg(xb4 + it * 2 + 0);
        const int4 ib = __ldg(xb4 + it * 2 + 1);
        const float4 v0 = __ldg(emb4 + (size_t)ia.x * EMB4 + d);
        const float4 v1 = __ldg(emb4 + (size_t)ia.y * EMB4 + d);
        const float4 v2 = __ldg(emb4 + (size_t)ia.z * EMB4 + d);
        const float4 v3 = __ldg(emb4 + (size_t)ia.w * EMB4 + d);
        const float4 v4 = __ldg(emb4 + (size_t)ib.x * EMB4 + d);
        const float4 v5 = __ldg(emb4 + (size_t)ib.y * EMB4 + d);
        const float4 v6 = __ldg(emb4 + (size_t)ib.z * EMB4 + d);
        const float4 v7 = __ldg(emb4 + (size_t)ib.w * EMB4 + d);
        a0.x += v0.x; a0.y += v0.y; a0.z += v0.z; a0.w += v0.w;
        a1.x += v1.x; a1.y += v1.y; a1.z += v1.z; a1.w += v1.w;
        a2.x += v2.x; a2.y += v2.y; a2.z += v2.z; a2.w += v2.w;
        a3.x += v3.x; a3.y += v3.y; a3.z += v3.z; a3.w += v3.w;
        a4.x += v4.x; a4.y += v4.y; a4.z += v4.z; a4.w += v4.w;
        a5.x += v5.x; a5.y += v5.y; a5.z += v5.z; a5.w += v5.w;
        a6.x += v6.x; a6.y += v6.y; a6.z += v6.z; a6.w += v6.w;
        a7.x += v7.x; a7.y += v7.y; a7.z += v7.z; a7.w += v7.w;
    }

    const float inv = 1.0f / (float)__ldg(lengths + b);
    float4 r;
    r.x = (a0.x + a1.x + a2.x + a3.x + a4.x + a5.x + a6.x + a7.x) * inv;
    r.y = (a0.y + a1.y + a2.y + a3.y + a4.y + a5.y + a6.y + a7.y) * inv;
    r.z = (a0.z + a1.z + a2.z + a3.z + a4.z + a5.z + a6.z + a7.z) * inv;
    r.w = (a0.w + a1.w + a2.w + a3.w + a4.w + a5.w + a6.w + a7.w) * inv;
    g_rep4[gid] = r;
}

// ---------------------------------------------------------------------------
// Kernel 2: logits = relu(rep @ W1 + b1) @ W2 + b2.
// SPB2=4 -> grid 512 (~7 warps/SMSP)  AND  LDG.128 W1 (16 FMA per load).
// Thread (jg 0..31, c 0..7): 4 output cols x 4 samples, d-chunk of 38.
// ---------------------------------------------------------------------------
__global__ __launch_bounds__(256) void mlp_kernel(
    const float* __restrict__ W1,   // [EMB, HID]
    const float* __restrict__ b1,   // [HID]
    const float* __restrict__ W2,   // [HID, OUTD]
    const float* __restrict__ b2,   // [OUTD]
    float*       __restrict__ out)  // [B, OUTD]
{
    __shared__ float repT[EMB][SPB2];          // 4.8 KB (16B rows -> LDS.128)
    __shared__ float hpart[DCH][SPB2][HID];    // 16 KB
    __shared__ float hbuf[SPB2][HID];          // 2 KB

    const int tid = threadIdx.x;
    const int b0  = blockIdx.x * SPB2;
    const float* rep = (const float*)g_rep4;

    // load rep tile (coalesced, transpose into smem)
    for (int i = tid; i < SPB2 * EMB; i += 256) {
        const int s = i / EMB;
        const int d = i - s * EMB;
        repT[d][s] = rep[(size_t)(b0 + s) * EMB + d];
    }
    __syncthreads();

    // GEMM1
    {
        const int jg = tid & 31;               // cols 4jg..4jg+3
        const int c  = tid >> 5;               // d-chunk 0..7
        const int d0 = c * 38;
        const int d1 = (d0 + 38 < EMB) ? (d0 + 38) : EMB;   // last = 34

        float4 acc[SPB2];
        #pragma unroll
        for (int s = 0; s < SPB2; ++s) acc[s] = make_float4(0.f, 0.f, 0.f, 0.f);

        const float4* W14 = (const float4*)W1;  // [EMB][32] float4

        float4 w = __ldg(&W14[(size_t)d0 * 32 + jg]);   // prefetch

        #pragma unroll 2
        for (int d = d0; d < d1; ++d) {
            const float4 wc = w;
            if (d + 1 < d1) w = __ldg(&W14[(size_t)(d + 1) * 32 + jg]);
            const float4 r = *(const float4*)&repT[d][0];    // broadcast LDS.128
            acc[0].x += r.x * wc.x; acc[0].y += r.x * wc.y; acc[0].z += r.x * wc.z; acc[0].w += r.x * wc.w;
            acc[1].x += r.y * wc.x; acc[1].y += r.y * wc.y; acc[1].z += r.y * wc.z; acc[1].w += r.y * wc.w;
            acc[2].x += r.z * wc.x; acc[2].y += r.z * wc.y; acc[2].z += r.z * wc.z; acc[2].w += r.z * wc.w;
            acc[3].x += r.w * wc.x; acc[3].y += r.w * wc.y; acc[3].z += r.w * wc.z; acc[3].w += r.w * wc.w;
        }

        #pragma unroll
        for (int s = 0; s < SPB2; ++s)
            *(float4*)&hpart[c][s][4 * jg] = acc[s];    // STS.128, conflict-free
    }
    __syncthreads();

    // combine partials + bias + relu
    for (int i = tid; i < SPB2 * HID; i += 256) {
        const int s = i >> 7;
        const int j = i & (HID - 1);
        float v = __ldg(&b1[j]);
        #pragma unroll
        for (int c = 0; c < DCH; ++c) v += hpart[c][s][j];
        hbuf[s][j] = v > 0.0f ? v : 0.0f;
    }
    __syncthreads();

    // GEMM2 tail: 80 threads compute 4 samples x 20 outputs
    if (tid < SPB2 * OUTD) {
        const int s = tid / OUTD;
        const int o = tid - s * OUTD;
        float a0 = __ldg(&b2[o]), a1 = 0.f, a2 = 0.f, a3 = 0.f;
        #pragma unroll 4
        for (int k = 0; k < HID; k += 4) {
            a0 += hbuf[s][k + 0] * __ldg(&W2[(size_t)(k + 0) * OUTD + o]);
            a1 += hbuf[s][k + 1] * __ldg(&W2[(size_t)(k + 1) * OUTD + o]);
            a2 += hbuf[s][k + 2] * __ldg(&W2[(size_t)(k + 2) * OUTD + o]);
            a3 += hbuf[s][k + 3] * __ldg(&W2[(size_t)(k + 3) * OUTD + o]);
        }
        out[(size_t)(b0 + s) * OUTD + o] = (a0 + a1) + (a2 + a3);
    }
}

extern "C" void kernel_launch(void* const* d_in, const int* in_sizes, int n_in,
                              void* d_out, int out_size)
{
    const int*    x       = (const int*)    d_in[0];
    const int*    lengths = (const int*)    d_in[1];
    const float4* emb4    = (const float4*) d_in[2];
    const float*  W1      = (const float*)  d_in[3];
    const float*  b1      = (const float*)  d_in[4];
    const float*  W2      = (const float*)  d_in[5];
    const float*  b2      = (const float*)  d_in[6];
    float*        out     = (float*)        d_out;

    const int gather_items = BSZ * EMB4;                    // 153600
    gather_kernel<<<(gather_items + 255) / 256, 256>>>(x, lengths, emb4);
    mlp_kernel<<<BSZ / SPB2, 256>>>(W1, b1, W2, b2, out);   // 512 blocks
}

// round 9
// speedup vs baseline: 1.4904x; 1.0420x over previous
#include <cuda_runtime.h>
#include <cuda_bf16.h>

#define VOCAB 100000
#define EMB   300
#define BSZ   2048
#define SEQL  200
#define HID   128
#define OUTD  20

#define EMB4  (EMB / 4)          // 75 float4 per row
#define SPB2  4                  // samples per MLP block -> grid 512
#define DCH   10                 // d-chunks of exactly 30 rows (10*30=300)
#define MLPT  320                // MLP block threads = 32 jg x 10 c

// rep scratch (device global — no allocation allowed)
__device__ float4 g_rep4[BSZ * EMB4];

// ---------------------------------------------------------------------------
// Kernel 1: embedding-bag mean.  At the LTS cap (12.9 TB/s warm) — unchanged.
// ---------------------------------------------------------------------------
__global__ __launch_bounds__(256) void gather_kernel(
    const int*    __restrict__ x,        // [B, L]
    const int*    __restrict__ lengths,  // [B]
    const float4* __restrict__ emb4)     // [VOCAB, 75]
{
    const int gid = blockIdx.x * 256 + threadIdx.x;
    if (gid >= BSZ * EMB4) return;
    const int b = gid / EMB4;
    const int d = gid - b * EMB4;

    const int4* xb4 = (const int4*)(x + (size_t)b * SEQL);

    float4 a0 = make_float4(0.f, 0.f, 0.f, 0.f);
    float4 a1 = a0, a2 = a0, a3 = a0, a4 = a0, a5 = a0, a6 = a0, a7 = a0;

    #pragma unroll 1
    for (int it = 0; it < 25; ++it) {
        const int4 ia = __ldg(xb4 + it * 2 + 0);
        const int4 ib = __ldg(xb4 + it * 2 + 1);
        const float4 v0 = __ldg(emb4 + (size_t)ia.x * EMB4 + d);
        const float4 v1 = __ldg(emb4 + (size_t)ia.y * EMB4 + d);
        const float4 v2 = __ldg(emb4 + (size_t)ia.z * EMB4 + d);
        const float4 v3 = __ldg(emb4 + (size_t)ia.w * EMB4 + d);
        const float4 v4 = __ldg(emb4 + (size_t)ib.x * EMB4 + d);
        const float4 v5 = __ldg(emb4 + (size_t)ib.y * EMB4 + d);
        const float4 v6 = __ldg(emb4 + (size_t)ib.z * EMB4 + d);
        const float4 v7 = __ldg(emb4 + (size_t)ib.w * EMB4 + d);
        a0.x += v0.x; a0.y += v0.y; a0.z += v0.z; a0.w += v0.w;
        a1.x += v1.x; a1.y += v1.y; a1.z += v1.z; a1.w += v1.w;
        a2.x += v2.x; a2.y += v2.y; a2.z += v2.z; a2.w += v2.w;
        a3.x += v3.x; a3.y += v3.y; a3.z += v3.z; a3.w += v3.w;
        a4.x += v4.x; a4.y += v4.y; a4.z += v4.z; a4.w += v4.w;
        a5.x += v5.x; a5.y += v5.y; a5.z += v5.z; a5.w += v5.w;
        a6.x += v6.x; a6.y += v6.y; a6.z += v6.z; a6.w += v6.w;
        a7.x += v7.x; a7.y += v7.y; a7.z += v7.z; a7.w += v7.w;
    }

    const float inv = 1.0f / (float)__ldg(lengths + b);
    float4 r;
    r.x = (a0.x + a1.x + a2.x + a3.x + a4.x + a5.x + a6.x + a7.x) * inv;
    r.y = (a0.y + a1.y + a2.y + a3.y + a4.y + a5.y + a6.y + a7.y) * inv;
    r.z = (a0.z + a1.z + a2.z + a3.z + a4.z + a5.z + a6.z + a7.z) * inv;
    r.w = (a0.w + a1.w + a2.w + a3.w + a4.w + a5.w + a6.w + a7.w) * inv;
    g_rep4[gid] = r;
}

// ---------------------------------------------------------------------------
// Kernel 2: logits = relu(rep @ W1 + b1) @ W2 + b2.
// 320 threads = 32 column-groups x 10 d-chunks of EXACTLY 30 rows.
// Fully unrolled, branch-free, W1 + rep both prefetched 1 iter ahead.
// ---------------------------------------------------------------------------
__global__ __launch_bounds__(MLPT) void mlp_kernel(
    const float* __restrict__ W1,   // [EMB, HID]
    const float* __restrict__ b1,   // [HID]
    const float* __restrict__ W2,   // [HID, OUTD]
    const float* __restrict__ b2,   // [OUTD]
    float*       __restrict__ out)  // [B, OUTD]
{
    __shared__ __align__(16) float repT[EMB][SPB2];         // 4.8 KB
    __shared__ __align__(16) float hpart[DCH][SPB2][HID];   // 20 KB
    __shared__ float hbuf[SPB2][HID];                       // 2 KB

    const int tid = threadIdx.x;
    const int b0  = blockIdx.x * SPB2;

    // ---- load rep tile: 300 float4 loads, transpose into smem -------------
    if (tid < SPB2 * EMB4) {
        const int s = tid / EMB4;
        const int d = tid - s * EMB4;
        const float4 v = g_rep4[(size_t)(b0 + s) * EMB4 + d];
        repT[4 * d + 0][s] = v.x;
        repT[4 * d + 1][s] = v.y;
        repT[4 * d + 2][s] = v.z;
        repT[4 * d + 3][s] = v.w;
    }
    __syncthreads();

    // ---- GEMM1: warp = d-chunk (30 rows), lane = 4-col group ---------------
    {
        const int jg = tid & 31;               // cols 4jg..4jg+3
        const int c  = tid >> 5;               // d-chunk 0..9
        const int d0 = c * 30;

        float4 acc[SPB2];
        #pragma unroll
        for (int s = 0; s < SPB2; ++s) acc[s] = make_float4(0.f, 0.f, 0.f, 0.f);

        const float4* W14 = (const float4*)W1;  // [EMB][32] float4

        // prefetch iteration 0
        float4 w = __ldg(&W14[(size_t)d0 * 32 + jg]);
        float4 r = *(const float4*)&repT[d0][0];

        #pragma unroll
        for (int k = 0; k < 30; ++k) {
            const float4 wc = w;
            const float4 rc = r;
            const int dn = d0 + ((k + 1) % 30);      // compile-time; wraps to d0
            w = __ldg(&W14[(size_t)dn * 32 + jg]);   // prefetch next W1 row
            r = *(const float4*)&repT[dn][0];        // prefetch next rep row
            acc[0].x += rc.x * wc.x; acc[0].y += rc.x * wc.y; acc[0].z += rc.x * wc.z; acc[0].w += rc.x * wc.w;
            acc[1].x += rc.y * wc.x; acc[1].y += rc.y * wc.y; acc[1].z += rc.y * wc.z; acc[1].w += rc.y * wc.w;
            acc[2].x += rc.z * wc.x; acc[2].y += rc.z * wc.y; acc[2].z += rc.z * wc.z; acc[2].w += rc.z * wc.w;
            acc[3].x += rc.w * wc.x; acc[3].y += rc.w * wc.y; acc[3].z += rc.w * wc.z; acc[3].w += rc.w * wc.w;
        }

        // conflict-free STS.128 (lane jg -> consecutive 16B)
        #pragma unroll
        for (int s = 0; s < SPB2; ++s)
            *(float4*)&hpart[c][s][4 * jg] = acc[s];
    }
    __syncthreads();

    // ---- combine partials + bias + relu ------------------------------------
    for (int i = tid; i < SPB2 * HID; i += MLPT) {
        const int s = i >> 7;
        const int j = i & (HID - 1);
        float v = __ldg(&b1[j]);
        #pragma unroll
        for (int c = 0; c < DCH; ++c) v += hpart[c][s][j];
        hbuf[s][j] = v > 0.0f ? v : 0.0f;
    }
    __syncthreads();

    // ---- GEMM2 tail: 80 threads, 4 samples x 20 outputs ---------------------
    if (tid < SPB2 * OUTD) {
        const int s = tid / OUTD;
        const int o = tid - s * OUTD;
        float a0 = __ldg(&b2[o]), a1 = 0.f, a2 = 0.f, a3 = 0.f;
        #pragma unroll 4
        for (int k = 0; k < HID; k += 4) {
            a0 += hbuf[s][k + 0] * __ldg(&W2[(size_t)(k + 0) * OUTD + o]);
            a1 += hbuf[s][k + 1] * __ldg(&W2[(size_t)(k + 1) * OUTD + o]);
            a2 += hbuf[s][k + 2] * __ldg(&W2[(size_t)(k + 2) * OUTD + o]);
            a3 += hbuf[s][k + 3] * __ldg(&W2[(size_t)(k + 3) * OUTD + o]);
        }
        out[(size_t)(b0 + s) * OUTD + o] = (a0 + a1) + (a2 + a3);
    }
}

extern "C" void kernel_launch(void* const* d_in, const int* in_sizes, int n_in,
                              void* d_out, int out_size)
{
    const int*    x       = (const int*)    d_in[0];
    const int*    lengths = (const int*)    d_in[1];
    const float4* emb4    = (const float4*) d_in[2];
    const float*  W1      = (const float*)  d_in[3];
    const float*  b1      = (const float*)  d_in[4];
    const float*  W2      = (const float*)  d_in[5];
    const float*  b2      = (const float*)  d_in[6];
    float*        out     = (float*)        d_out;

    const int gather_items = BSZ * EMB4;                    // 153600
    gather_kernel<<<(gather_items + 255) / 256, 256>>>(x, lengths, emb4);
    mlp_kernel<<<BSZ / SPB2, MLPT>>>(W1, b1, W2, b2, out);  // 512 blocks
}